// round 1
// baseline (speedup 1.0000x reference)
#include <cuda_runtime.h>
#include <cuda_bf16.h>
#include <math.h>

#define NNODES 1200000
#define FFLOPS 1000000
#define NXB 512
#define NYB 512
#define NCKB 16
#define NCEB 8
#define MAPSZ (NXB * NYB * NCKB * NCEB)   // 33,554,432 floats = 128 MB
#define SQRT2_INV 0.70710678118654752440f
#define INV_SLICE_CAP (1.0f / 16.0f)

// 128 MB scratch demand map (zero-initialized .bss; re-zeroed every launch)
__device__ float g_dem_map[MAPSZ];

// Per-axis truncated-Gaussian window weights.
// Edges e[k] = erf((b0-2+k - c)/sqrt(2)), k=0..5; w[i] = (e[i+1]-e[i])/(e[5]-e[0]).
__device__ __forceinline__ void axis_weights(float c, int* b0_out, float* w) {
    int b0 = (int)floorf(c);
    *b0_out = b0;
    float e[6];
#pragma unroll
    for (int k = 0; k < 6; k++) {
        float edge = (float)(b0 - 2 + k);
        e[k] = erff((edge - c) * SQRT2_INV);
    }
    float inv = 1.0f / (e[5] - e[0]);
#pragma unroll
    for (int i = 0; i < 5; i++) {
        w[i] = (e[i + 1] - e[i]) * inv;
    }
}

__global__ __launch_bounds__(256) void scatter_kernel(
    const float* __restrict__ pos,
    const int* __restrict__ flop_indices,
    const int* __restrict__ ctrl,
    const float* __restrict__ nsx,
    const float* __restrict__ nsy)
{
    int f = blockIdx.x * blockDim.x + threadIdx.x;
    if (f >= FFLOPS) return;

    int fi = flop_indices[f];
    float cx = pos[fi] + 0.5f * nsx[fi];
    float cy = pos[NNODES + fi] + 0.5f * nsy[fi];

    int bx0, by0;
    float wx[5], wy[5];
    axis_weights(cx, &bx0, wx);
    axis_weights(cy, &by0, wy);

    // ctrlSets values are nonnegative; % power-of-two == mask
    int cksr = ctrl[3 * f + 1] & (NCKB - 1);
    int ce   = ctrl[3 * f + 2] & (NCEB - 1);
    int ckce = cksr * NCEB + ce;

#pragma unroll
    for (int i = 0; i < 5; i++) {
        int bx = min(max(bx0 - 2 + i, 0), NXB - 1);   // clipped — matches reference scatter
        int base_x = bx * (NYB * NCKB * NCEB) + ckce;
        float wxi = wx[i];
#pragma unroll
        for (int j = 0; j < 5; j++) {
            int by = min(max(by0 - 2 + j, 0), NYB - 1);
            atomicAdd(&g_dem_map[base_x + by * (NCKB * NCEB)], wxi * wy[j]);
        }
    }
}

__global__ __launch_bounds__(256) void gather_kernel(
    const float* __restrict__ pos,
    const int* __restrict__ flop_indices,
    const int* __restrict__ ctrl,
    const float* __restrict__ nsx,
    const float* __restrict__ nsy,
    float* __restrict__ out)
{
    int f = blockIdx.x * blockDim.x + threadIdx.x;
    if (f >= FFLOPS) return;

    int fi = flop_indices[f];
    float cx = pos[fi] + 0.5f * nsx[fi];
    float cy = pos[NNODES + fi] + 0.5f * nsy[fi];

    int bx0 = (int)floorf(cx) - 2;
    int by0 = (int)floorf(cy) - 2;

    int cksr = ctrl[3 * f + 1] & (NCKB - 1);
    int ce   = ctrl[3 * f + 2] & (NCEB - 1);
    int ckce = cksr * NCEB + ce;

    float s = 0.0f;
#pragma unroll
    for (int i = 0; i < 5; i++) {
        int bx = bx0 + i;
        bool okx = (bx >= 0) && (bx < NXB);
        int base_x = bx * (NYB * NCKB * NCEB) + ckce;
#pragma unroll
        for (int j = 0; j < 5; j++) {
            int by = by0 + j;
            bool ok = okx && (by >= 0) && (by < NYB);
            if (ok) {
                s += g_dem_map[base_x + by * (NCKB * NCEB)];
            }
        }
    }
    // resource_areas scatter at fi (indices are unique arange, but honor the array)
    atomicAdd(&out[fi], s * INV_SLICE_CAP);
}

extern "C" void kernel_launch(void* const* d_in, const int* in_sizes, int n_in,
                              void* d_out, int out_size)
{
    const float* pos  = (const float*)d_in[0];
    const int*   fidx = (const int*)d_in[1];
    const int*   ctrl = (const int*)d_in[2];
    const float* nsx  = (const float*)d_in[3];
    const float* nsy  = (const float*)d_in[4];
    float* out = (float*)d_out;

    // Zero the demand map and the output (d_out is poisoned to 0xAA)
    void* map_ptr = nullptr;
    cudaGetSymbolAddress(&map_ptr, g_dem_map);
    cudaMemsetAsync(map_ptr, 0, (size_t)MAPSZ * sizeof(float), 0);
    cudaMemsetAsync(out, 0, (size_t)out_size * sizeof(float), 0);

    const int TPB = 256;
    int blocks_f = (FFLOPS + TPB - 1) / TPB;
    scatter_kernel<<<blocks_f, TPB>>>(pos, fidx, ctrl, nsx, nsy);
    gather_kernel<<<blocks_f, TPB>>>(pos, fidx, ctrl, nsx, nsy, out);
}

// round 2
// speedup vs baseline: 2.1115x; 2.1115x over previous
#include <cuda_runtime.h>
#include <cuda_bf16.h>
#include <math.h>

#define NNODES 1200000
#define FFLOPS 1000000
#define NXB 512
#define NYB 512
#define NCKB 16
#define NCEB 8
#define MAPSZ (NXB * NYB * NCKB * NCEB)   // 33,554,432 floats = 128 MB
#define SQRT2_INV 0.70710678118654752440f
#define INV_SLICE_CAP (1.0f / 16.0f)

// Scratch demand map, layout [ckce][bx][by] (y contiguous). 16B-aligned for v4 atomics.
__device__ __align__(16) float g_dem_map[MAPSZ];

// Per-axis truncated-Gaussian window weights.
__device__ __forceinline__ void axis_weights(float c, int* b0_out, float* w) {
    int b0 = (int)floorf(c);
    *b0_out = b0;
    float e[6];
#pragma unroll
    for (int k = 0; k < 6; k++) {
        float edge = (float)(b0 - 2 + k);
        e[k] = erff((edge - c) * SQRT2_INV);
    }
    float inv = 1.0f / (e[5] - e[0]);
#pragma unroll
    for (int i = 0; i < 5; i++) {
        w[i] = (e[i + 1] - e[i]) * inv;
    }
}

// Place wy[0..4] at positions off..off+4 of an 8-lane window (off in 0..3).
__device__ __forceinline__ void shift_window(const float* wy, int off, float* y8) {
#pragma unroll
    for (int k = 0; k < 8; k++) y8[k] = 0.0f;
    switch (off) {
        case 0: y8[0]=wy[0]; y8[1]=wy[1]; y8[2]=wy[2]; y8[3]=wy[3]; y8[4]=wy[4]; break;
        case 1: y8[1]=wy[0]; y8[2]=wy[1]; y8[3]=wy[2]; y8[4]=wy[3]; y8[5]=wy[4]; break;
        case 2: y8[2]=wy[0]; y8[3]=wy[1]; y8[4]=wy[2]; y8[5]=wy[3]; y8[6]=wy[4]; break;
        default:y8[3]=wy[0]; y8[4]=wy[1]; y8[5]=wy[2]; y8[6]=wy[3]; y8[7]=wy[4]; break;
    }
}

__device__ __forceinline__ void red_v4(float* ptr, float a, float b, float c, float d) {
    asm volatile("red.global.add.v4.f32 [%0], {%1, %2, %3, %4};"
                 :: "l"(ptr), "f"(a), "f"(b), "f"(c), "f"(d) : "memory");
}

__global__ __launch_bounds__(256) void scatter_kernel(
    const float* __restrict__ pos,
    const int* __restrict__ flop_indices,
    const int* __restrict__ ctrl,
    const float* __restrict__ nsx,
    const float* __restrict__ nsy)
{
    int f = blockIdx.x * blockDim.x + threadIdx.x;
    if (f >= FFLOPS) return;

    int fi = flop_indices[f];
    float cx = pos[fi] + 0.5f * nsx[fi];
    float cy = pos[NNODES + fi] + 0.5f * nsy[fi];

    int bx0, by0c;
    float wx[5], wy[5];
    axis_weights(cx, &bx0, wx);
    axis_weights(cy, &by0c, wy);
    int bxs = bx0 - 2;
    int by0 = by0c - 2;

    int cksr = ctrl[3 * f + 1] & (NCKB - 1);
    int ce   = ctrl[3 * f + 2] & (NCEB - 1);
    int plane = (cksr * NCEB + ce) * (NXB * NYB);   // [ckce][bx][by] layout

    bool fasty = (by0 >= 0) && (by0 + 4 < NYB);
    if (fasty) {
        int a   = by0 & ~3;
        int off = by0 - a;
        float y8[8];
        shift_window(wy, off, y8);
#pragma unroll
        for (int i = 0; i < 5; i++) {
            int bx = min(max(bxs + i, 0), NXB - 1);   // clipped, matches reference scatter
            float* base = &g_dem_map[plane + bx * NYB + a];
            float wxi = wx[i];
            red_v4(base,     y8[0]*wxi, y8[1]*wxi, y8[2]*wxi, y8[3]*wxi);
            red_v4(base + 4, y8[4]*wxi, y8[5]*wxi, y8[6]*wxi, y8[7]*wxi);
        }
    } else {
        // rare y-clipped path: scalar clamped taps
#pragma unroll
        for (int i = 0; i < 5; i++) {
            int bx = min(max(bxs + i, 0), NXB - 1);
            int rowbase = plane + bx * NYB;
            float wxi = wx[i];
#pragma unroll
            for (int j = 0; j < 5; j++) {
                int by = min(max(by0 + j, 0), NYB - 1);
                atomicAdd(&g_dem_map[rowbase + by], wxi * wy[j]);
            }
        }
    }
}

__global__ __launch_bounds__(256) void gather_kernel(
    const float* __restrict__ pos,
    const int* __restrict__ flop_indices,
    const int* __restrict__ ctrl,
    const float* __restrict__ nsx,
    const float* __restrict__ nsy,
    float* __restrict__ out)
{
    int f = blockIdx.x * blockDim.x + threadIdx.x;
    if (f >= FFLOPS) return;

    int fi = flop_indices[f];
    float cx = pos[fi] + 0.5f * nsx[fi];
    float cy = pos[NNODES + fi] + 0.5f * nsy[fi];

    int bxs = (int)floorf(cx) - 2;
    int by0 = (int)floorf(cy) - 2;

    int cksr = ctrl[3 * f + 1] & (NCKB - 1);
    int ce   = ctrl[3 * f + 2] & (NCEB - 1);
    int plane = (cksr * NCEB + ce) * (NXB * NYB);

    float s = 0.0f;
    bool fasty = (by0 >= 0) && (by0 + 4 < NYB);
    if (fasty) {
        int a   = by0 & ~3;
        int off = by0 - a;
        // 1.0 mask at lanes off..off+4
        float ones[5] = {1.f, 1.f, 1.f, 1.f, 1.f};
        float m8[8];
        shift_window(ones, off, m8);
#pragma unroll
        for (int i = 0; i < 5; i++) {
            int bx = bxs + i;
            if (bx < 0 || bx >= NXB) continue;    // unclipped mask in x
            const float4* base = (const float4*)&g_dem_map[plane + bx * NYB + a];
            float4 v0 = base[0];
            float4 v1 = base[1];
            s += v0.x*m8[0] + v0.y*m8[1] + v0.z*m8[2] + v0.w*m8[3]
               + v1.x*m8[4] + v1.y*m8[5] + v1.z*m8[6] + v1.w*m8[7];
        }
    } else {
#pragma unroll
        for (int i = 0; i < 5; i++) {
            int bx = bxs + i;
            if (bx < 0 || bx >= NXB) continue;
            int rowbase = plane + bx * NYB;
#pragma unroll
            for (int j = 0; j < 5; j++) {
                int by = by0 + j;
                if (by >= 0 && by < NYB) s += g_dem_map[rowbase + by];
            }
        }
    }
    out[fi] = s * INV_SLICE_CAP;   // flop_indices is a permutation-free arange; unique
}

extern "C" void kernel_launch(void* const* d_in, const int* in_sizes, int n_in,
                              void* d_out, int out_size)
{
    const float* pos  = (const float*)d_in[0];
    const int*   fidx = (const int*)d_in[1];
    const int*   ctrl = (const int*)d_in[2];
    const float* nsx  = (const float*)d_in[3];
    const float* nsy  = (const float*)d_in[4];
    float* out = (float*)d_out;

    void* map_ptr = nullptr;
    cudaGetSymbolAddress(&map_ptr, g_dem_map);
    cudaMemsetAsync(map_ptr, 0, (size_t)MAPSZ * sizeof(float), 0);
    cudaMemsetAsync(out, 0, (size_t)out_size * sizeof(float), 0);

    const int TPB = 256;
    int blocks_f = (FFLOPS + TPB - 1) / TPB;
    scatter_kernel<<<blocks_f, TPB>>>(pos, fidx, ctrl, nsx, nsy);
    gather_kernel<<<blocks_f, TPB>>>(pos, fidx, ctrl, nsx, nsy, out);
}